// round 9
// baseline (speedup 1.0000x reference)
#include <cuda_runtime.h>
#include <cuda_fp16.h>

// ---------------- problem dims ----------------
constexpr int B = 2, D1 = 8, D2 = 16, D3 = 32, D4 = 32, F = 8, H = 16, H2 = 32;
constexpr int NV = B * D1 * D2 * D3 * D4;  // 262144 voxels
constexpr float LRELU = 0.01f;

// ---------------- static scratch ----------------
__device__ unsigned g_actA[(long)NV * 8];         // conv1 input
__device__ unsigned g_actB[(long)NV * 8];         // conv2 input
__device__ unsigned g_actC[(long)NV * 16];        // conv3 input (2 planes)
__device__ float    g_fout[(long)NV * 32];        // conv fp32 output (reused)
// expanded fp16 weights: [slab][dy][cout][44 u32]
__device__ unsigned g_wx1[25 * 5 * 16 * 44];
__device__ unsigned g_wx2[25 * 5 * 32 * 44];
__device__ unsigned g_wx3[50 * 5 * 16 * 44];
__device__ double g_sum[3 * 32];
__device__ double g_ssq[3 * 32];

// ---------------- helpers ----------------
__device__ __forceinline__ unsigned packh2(float a, float b) {
    __half2 h = __floats2half2_rn(a, b);
    return *(unsigned*)&h;
}
__device__ __forceinline__ void mma_f16(float* c, unsigned a0, unsigned a1, unsigned a2, unsigned a3,
                                        unsigned b0, unsigned b1) {
    asm volatile(
        "mma.sync.aligned.m16n8k16.row.col.f32.f16.f16.f32 "
        "{%0,%1,%2,%3},{%4,%5,%6,%7},{%8,%9},{%0,%1,%2,%3};"
        : "+f"(c[0]), "+f"(c[1]), "+f"(c[2]), "+f"(c[3])
        : "r"(a0), "r"(a1), "r"(a2), "r"(a3), "r"(b0), "r"(b1));
}
__device__ __forceinline__ void ldsm4(unsigned* r, unsigned addr) {
    asm volatile("ldmatrix.sync.aligned.m8n8.x4.shared.b16 {%0,%1,%2,%3}, [%4];"
                 : "=r"(r[0]), "=r"(r[1]), "=r"(r[2]), "=r"(r[3]) : "r"(addr));
}
__device__ __forceinline__ void ldsm2(unsigned* r, unsigned addr) {
    asm volatile("ldmatrix.sync.aligned.m8n8.x2.shared.b16 {%0,%1}, [%2];"
                 : "=r"(r[0]), "=r"(r[1]) : "r"(addr));
}
__device__ __forceinline__ unsigned smem_u32(const void* p) {
    unsigned a;
    asm("{ .reg .u64 t; cvta.to.shared.u64 t, %1; cvt.u32.u64 %0, t; }" : "=r"(a) : "l"(p));
    return a;
}

// ---------------- small kernels ----------------
__global__ void zero_stats_kernel(double* s, double* q) {
    int i = threadIdx.x;
    if (i < 96) { s[i] = 0.0; q[i] = 0.0; }
}

__global__ void wext_kernel(const float* __restrict__ W, unsigned* __restrict__ dst,
                            int COUT, int CINF, int n) {
    int i = blockIdx.x * blockDim.x + threadIdx.x;
    if (i >= n) return;
    int j  = i % 44;
    int co = (i / 44) % COUT;
    int dy = (i / (44 * COUT)) % 5;
    int s  = i / (220 * COUT);
    int g = s / 25, tap = s % 25, dt = tap / 5, dz = tap % 5;
    unsigned val = 0;
    if (j < 40) {
        int dx = j / 8, ci = 2 * (j % 8);
        long base = dt * 125 + dz * 25 + dy * 5 + dx;
        float w0 = W[((long)co * CINF + g * 16 + ci) * 625 + base];
        float w1 = W[((long)co * CINF + g * 16 + ci + 1) * 625 + base];
        val = packh2(w0, w1);
    }
    dst[i] = val;
}

__global__ void embed_kernel(const float* __restrict__ x, const float* __restrict__ we,
                             const float* __restrict__ be, unsigned* __restrict__ act) {
    __shared__ float sw[F * H];
    __shared__ float sb[H];
    if (threadIdx.x < F * H) sw[threadIdx.x] = we[threadIdx.x];
    if (threadIdx.x < H) sb[threadIdx.x] = be[threadIdx.x];
    __syncthreads();
    int v = blockIdx.x * blockDim.x + threadIdx.x;
    if (v >= NV) return;
    const float4* xp = (const float4*)(x + v * F);
    float4 x0 = xp[0], x1 = xp[1];
    float xf[F] = {x0.x, x0.y, x0.z, x0.w, x1.x, x1.y, x1.z, x1.w};
    float o[H];
#pragma unroll
    for (int h = 0; h < H; h++) {
        float a = sb[h];
#pragma unroll
        for (int f = 0; f < F; f++) a += xf[f] * sw[f * H + h];
        o[h] = a;
    }
    unsigned p[8];
#pragma unroll
    for (int q = 0; q < 8; q++) p[q] = packh2(o[2*q], o[2*q+1]);
    uint4* dst = (uint4*)(act + (long)v * 8);
    dst[0] = make_uint4(p[0], p[1], p[2], p[3]);
    dst[1] = make_uint4(p[4], p[5], p[6], p[7]);
}

// ---------------- tensor-core 4D conv (fp16 k16, ldmatrix) + fused BN stats ----------------
template <int COUT, int SLABS>
__global__ void __launch_bounds__(256)
conv_mma_kernel(const unsigned* __restrict__ act, const unsigned* __restrict__ wext,
                const float* __restrict__ bias, float* __restrict__ fout,
                double* __restrict__ gsum, double* __restrict__ gssq) {
    constexpr int NT = COUT / 8;
    constexpr int SA_U32 = 12 * 36 * 12;          // 5184
    constexpr int SW_U32 = 5 * COUT * 44;
    extern __shared__ unsigned smem_u[];
    unsigned* sA = smem_u;
    unsigned* sW = smem_u + SA_U32;
    float* s_st  = (float*)(smem_u + SA_U32 + SW_U32);   // [2*COUT]

    int bi = blockIdx.x;
    int d3b = (bi & 3) * 8;
    int rest = bi >> 2;
    int d2 = rest & 15, d1 = (rest >> 4) & 7, b = rest >> 7;

    int tid = threadIdx.x, lane = tid & 31, wid = tid >> 5;
    int d3r0 = wid >> 1, h = wid & 1;
    int lq = lane >> 2, lr = lane & 3;

    // ldmatrix per-lane address constants (byte offsets)
    unsigned sAb = smem_u32(sA);
    unsigned sWb = smem_u32(sW);
    int mrow = (lane & 7) + ((lane >> 3) & 1) * 8;
    int khA  = lane >> 4;
    unsigned constA = (unsigned)((h * 16 + mrow) * 48 + khA * 16);
    int coB = lane & 7, khB = (lane >> 3) & 1, kaB = lane >> 4;
    unsigned constB = (unsigned)(coB * 176 + kaB * 32 + khB * 16);

    for (int i = tid; i < 2 * COUT; i += 256) s_st[i] = 0.f;

    float acc[2][NT][4];
#pragma unroll
    for (int t = 0; t < 2; t++)
#pragma unroll
        for (int n = 0; n < NT; n++) {
            float b0 = bias[n * 8 + 2 * lr], b1v = bias[n * 8 + 2 * lr + 1];
            acc[t][n][0] = b0; acc[t][n][1] = b1v; acc[t][n][2] = b0; acc[t][n][3] = b1v;
        }

    const uint4* actu4 = (const uint4*)act;
    const uint4* wxu4  = (const uint4*)wext;

    for (int s = 0; s < SLABS; s++) {
        int g = s / 25, tap = s % 25;
        int dt = tap / 5, dz = tap % 5;
        int d1s = d1 + dt - 2, d2s = d2 + dz - 2;
        bool v12 = ((unsigned)d1s < 8u) && ((unsigned)d2s < 16u);
        int pbase = g * NV;
        int vb = ((b * 8 + d1s) * 16 + d2s) * 1024;
        __syncthreads();
        // stage A: 12 srows x 36 d4p cells, 2 uint4 each
        for (int i = tid; i < 864; i += 256) {
            int q = i & 1, cell = i >> 1;
            int d4p = cell % 36, srow = cell / 36;
            int d3s = d3b + srow - 2;
            uint4 v = make_uint4(0, 0, 0, 0);
            if (v12 && (unsigned)d3s < 32u && d4p >= 2 && d4p < 34)
                v = actu4[((long)(pbase + vb + d3s * 32 + d4p - 2) << 1) + q];
            *(uint4*)(sA + cell * 12 + q * 4) = v;
        }
        // stage W slab
        {
            const uint4* wsrc = wxu4 + (long)s * (SW_U32 / 4);
            for (int i = tid; i < SW_U32 / 4; i += 256) ((uint4*)sW)[i] = wsrc[i];
        }
        __syncthreads();

#pragma unroll
        for (int dy = 0; dy < 5; dy++) {
            unsigned aT0 = sAb + (unsigned)((d3r0 + dy) * 1728) + constA;
            unsigned aT1 = aT0 + 4 * 1728;
            unsigned wB  = sWb + (unsigned)(dy * (COUT * 176)) + constB;
#pragma unroll
            for (int kcp = 0; kcp < 2; kcp++) {
                unsigned a0[4], a1[4], c0[4], c1[4];
                ldsm4(a0, aT0 + (2 * kcp) * 48);
                ldsm4(a1, aT0 + (2 * kcp + 1) * 48);
                ldsm4(c0, aT1 + (2 * kcp) * 48);
                ldsm4(c1, aT1 + (2 * kcp + 1) * 48);
#pragma unroll
                for (int n = 0; n < NT; n++) {
                    unsigned bq[4];
                    ldsm4(bq, wB + n * 1408 + (2 * kcp) * 32);
                    mma_f16(acc[0][n], a0[0], a0[1], a0[2], a0[3], bq[0], bq[1]);
                    mma_f16(acc[1][n], c0[0], c0[1], c0[2], c0[3], bq[0], bq[1]);
                    mma_f16(acc[0][n], a1[0], a1[1], a1[2], a1[3], bq[2], bq[3]);
                    mma_f16(acc[1][n], c1[0], c1[1], c1[2], c1[3], bq[2], bq[3]);
                }
            }
            // kc = 4
            {
                unsigned a0[4], c0[4];
                ldsm4(a0, aT0 + 4 * 48);
                ldsm4(c0, aT1 + 4 * 48);
#pragma unroll
                for (int n = 0; n < NT; n++) {
                    unsigned bq[2];
                    ldsm2(bq, wB + n * 1408 + 4 * 32);
                    mma_f16(acc[0][n], a0[0], a0[1], a0[2], a0[3], bq[0], bq[1]);
                    mma_f16(acc[1][n], c0[0], c0[1], c0[2], c0[3], bq[0], bq[1]);
                }
            }
        }
    }

    // epilogue: store fp32 + fused BN stats
    int vox0 = ((b * 8 + d1) * 16 + d2) * 1024 + d3b * 32;
#pragma unroll
    for (int t = 0; t < 2; t++) {
        int d3r = d3r0 + 4 * t;
        long base = (long)(vox0 + d3r * 32 + h * 16 + lq) * COUT + 2 * lr;
#pragma unroll
        for (int n = 0; n < NT; n++) {
            *(float2*)&fout[base + n * 8]            = make_float2(acc[t][n][0], acc[t][n][1]);
            *(float2*)&fout[base + 8 * COUT + n * 8] = make_float2(acc[t][n][2], acc[t][n][3]);
        }
    }
#pragma unroll
    for (int n = 0; n < NT; n++) {
        float s0 = 0.f, s1 = 0.f, q0 = 0.f, q1 = 0.f;
#pragma unroll
        for (int t = 0; t < 2; t++) {
            s0 += acc[t][n][0] + acc[t][n][2];
            s1 += acc[t][n][1] + acc[t][n][3];
            q0 += acc[t][n][0] * acc[t][n][0] + acc[t][n][2] * acc[t][n][2];
            q1 += acc[t][n][1] * acc[t][n][1] + acc[t][n][3] * acc[t][n][3];
        }
#pragma unroll
        for (int off = 16; off >= 4; off >>= 1) {
            s0 += __shfl_down_sync(0xffffffffu, s0, off);
            s1 += __shfl_down_sync(0xffffffffu, s1, off);
            q0 += __shfl_down_sync(0xffffffffu, q0, off);
            q1 += __shfl_down_sync(0xffffffffu, q1, off);
        }
        if (lq == 0) {
            int ch = n * 8 + 2 * lr;
            atomicAdd(&s_st[ch], s0);
            atomicAdd(&s_st[ch + 1], s1);
            atomicAdd(&s_st[COUT + ch], q0);
            atomicAdd(&s_st[COUT + ch + 1], q1);
        }
    }
    __syncthreads();
    if (tid < COUT)          atomicAdd(&gsum[tid], (double)s_st[tid]);
    else if (tid < 2 * COUT) atomicAdd(&gssq[tid - COUT], (double)s_st[tid]);
}

// ---------------- bn apply (+ leaky relu) -> fp16 planes ----------------
template <int C>
__global__ void bn_apply_kernel(const float* __restrict__ fout, const double* __restrict__ sum,
                                const double* __restrict__ ssq, const float* __restrict__ gamma,
                                const float* __restrict__ beta, unsigned* __restrict__ act) {
    constexpr int NPL = C / 16;
    __shared__ float sc[C], sh[C];
    int tid = threadIdx.x;
    if (tid < C) {
        double m   = sum[tid] / (double)NV;
        double var = ssq[tid] / (double)NV - m * m;
        double inv = 1.0 / sqrt(var + 1e-5);
        float s = gamma[tid] * (float)inv;
        sc[tid] = s;
        sh[tid] = beta[tid] - (float)m * s;
    }
    __syncthreads();
    long total  = (long)NV * NPL;
    long stride = (long)gridDim.x * blockDim.x;
    for (long id = blockIdx.x * (long)blockDim.x + tid; id < total; id += stride) {
        int vox = (int)(id % NV);
        int pl  = (int)(id / NV);
        const float4* src = (const float4*)&fout[(long)vox * C + pl * 16];
        float4 v0 = src[0], v1 = src[1], v2 = src[2], v3 = src[3];
        float vv[16] = {v0.x, v0.y, v0.z, v0.w, v1.x, v1.y, v1.z, v1.w,
                        v2.x, v2.y, v2.z, v2.w, v3.x, v3.y, v3.z, v3.w};
        unsigned p[8];
#pragma unroll
        for (int q = 0; q < 8; q++) {
            float r0 = vv[2*q]   * sc[pl*16 + 2*q]   + sh[pl*16 + 2*q];
            float r1 = vv[2*q+1] * sc[pl*16 + 2*q+1] + sh[pl*16 + 2*q+1];
            r0 = fmaxf(r0, LRELU * r0);
            r1 = fmaxf(r1, LRELU * r1);
            p[q] = packh2(r0, r1);
        }
        uint4* dst = (uint4*)&act[((long)pl * NV + vox) * 8];
        dst[0] = make_uint4(p[0], p[1], p[2], p[3]);
        dst[1] = make_uint4(p[4], p[5], p[6], p[7]);
    }
}

// ---------------- fused BN + leaky relu + projection (layer 3) ----------------
__global__ void bnproj_kernel(const float* __restrict__ fout, const double* __restrict__ sum,
                              const double* __restrict__ ssq, const float* __restrict__ gamma,
                              const float* __restrict__ beta, const float* __restrict__ wp,
                              const float* __restrict__ bp, float* __restrict__ out) {
    __shared__ float sc[H], sh[H], sw[H];
    __shared__ float sb;
    int tid = threadIdx.x;
    if (tid < H) {
        double m   = sum[tid] / (double)NV;
        double var = ssq[tid] / (double)NV - m * m;
        double inv = 1.0 / sqrt(var + 1e-5);
        float s = gamma[tid] * (float)inv;
        sc[tid] = s;
        sh[tid] = beta[tid] - (float)m * s;
        sw[tid] = wp[tid];
    }
    if (tid == 0) sb = bp[0];
    __syncthreads();
    int v = blockIdx.x * blockDim.x + tid;
    if (v >= NV) return;
    const float4* src = (const float4*)&fout[(long)v * H];
    float4 v0 = src[0], v1 = src[1], v2 = src[2], v3 = src[3];
    float vv[16] = {v0.x, v0.y, v0.z, v0.w, v1.x, v1.y, v1.z, v1.w,
                    v2.x, v2.y, v2.z, v2.w, v3.x, v3.y, v3.z, v3.w};
    float a = sb;
#pragma unroll
    for (int c = 0; c < H; c++) {
        float r = vv[c] * sc[c] + sh[c];
        r = fmaxf(r, LRELU * r);
        a += r * sw[c];
    }
    out[v] = a;
}

// ---------------- launch ----------------
extern "C" void kernel_launch(void* const* d_in, const int* in_sizes, int n_in,
                              void* d_out, int out_size) {
    const float* x      = (const float*)d_in[0];
    const float* w_emb  = (const float*)d_in[1];
    const float* b_emb  = (const float*)d_in[2];
    const float* W1     = (const float*)d_in[3];
    const float* b1     = (const float*)d_in[4];
    const float* g1     = (const float*)d_in[5];
    const float* be1    = (const float*)d_in[6];
    const float* W2     = (const float*)d_in[7];
    const float* b2     = (const float*)d_in[8];
    const float* g2     = (const float*)d_in[9];
    const float* be2    = (const float*)d_in[10];
    const float* W3     = (const float*)d_in[11];
    const float* b3     = (const float*)d_in[12];
    const float* g3     = (const float*)d_in[13];
    const float* be3    = (const float*)d_in[14];
    const float* w_proj = (const float*)d_in[15];
    const float* b_proj = (const float*)d_in[16];

    unsigned *actA, *actB, *actC, *wx1, *wx2, *wx3;
    float* fout;
    double *sums, *ssqs;
    cudaGetSymbolAddress((void**)&actA, g_actA);
    cudaGetSymbolAddress((void**)&actB, g_actB);
    cudaGetSymbolAddress((void**)&actC, g_actC);
    cudaGetSymbolAddress((void**)&fout, g_fout);
    cudaGetSymbolAddress((void**)&wx1, g_wx1);
    cudaGetSymbolAddress((void**)&wx2, g_wx2);
    cudaGetSymbolAddress((void**)&wx3, g_wx3);
    cudaGetSymbolAddress((void**)&sums, g_sum);
    cudaGetSymbolAddress((void**)&ssqs, g_ssq);

    cudaFuncSetAttribute(conv_mma_kernel<16, 25>, cudaFuncAttributeMaxDynamicSharedMemorySize, 34944);
    cudaFuncSetAttribute(conv_mma_kernel<32, 25>, cudaFuncAttributeMaxDynamicSharedMemorySize, 49152);
    cudaFuncSetAttribute(conv_mma_kernel<16, 50>, cudaFuncAttributeMaxDynamicSharedMemorySize, 34944);

    zero_stats_kernel<<<1, 128>>>(sums, ssqs);
    wext_kernel<<<(88000 + 255) / 256, 256>>>(W1, wx1, 16, 16, 88000);
    wext_kernel<<<(176000 + 255) / 256, 256>>>(W2, wx2, 32, 16, 176000);
    wext_kernel<<<(176000 + 255) / 256, 256>>>(W3, wx3, 16, 32, 176000);

    embed_kernel<<<NV / 256, 256>>>(x, w_emb, b_emb, actA);

    conv_mma_kernel<16, 25><<<1024, 256, 34944>>>(actA, wx1, b1, fout, sums + 0, ssqs + 0);
    bn_apply_kernel<16><<<1024, 256>>>(fout, sums + 0, ssqs + 0, g1, be1, actB);

    conv_mma_kernel<32, 25><<<1024, 256, 49152>>>(actB, wx2, b2, fout, sums + 32, ssqs + 32);
    bn_apply_kernel<32><<<2048, 256>>>(fout, sums + 32, ssqs + 32, g2, be2, actC);

    conv_mma_kernel<16, 50><<<1024, 256, 34944>>>(actC, wx3, b3, fout, sums + 64, ssqs + 64);
    bnproj_kernel<<<NV / 256, 256>>>(fout, sums + 64, ssqs + 64, g3, be3, w_proj, b_proj, (float*)d_out);
}

// round 10
// speedup vs baseline: 1.3700x; 1.3700x over previous
#include <cuda_runtime.h>
#include <cuda_fp16.h>

// ---------------- problem dims ----------------
constexpr int B = 2, D1 = 8, D2 = 16, D3 = 32, D4 = 32, F = 8, H = 16, H2 = 32;
constexpr int NV = B * D1 * D2 * D3 * D4;  // 262144 voxels
constexpr float LRELU = 0.01f;

// ---------------- static scratch ----------------
__device__ unsigned g_actA[(long)NV * 8];         // conv1 input
__device__ unsigned g_actB[(long)NV * 8];         // conv2 input
__device__ unsigned g_actC[(long)NV * 16];        // conv3 input (2 planes)
__device__ float    g_fout[(long)NV * 32];        // conv fp32 output (reused)
// expanded fp16 weights: [slab][dy][cout][44 u32]
__device__ unsigned g_wx1[25 * 5 * 16 * 44];
__device__ unsigned g_wx2[25 * 5 * 32 * 44];
__device__ unsigned g_wx3[50 * 5 * 16 * 44];
__device__ double g_sum[3 * 32];
__device__ double g_ssq[3 * 32];

// ---------------- helpers ----------------
__device__ __forceinline__ unsigned packh2(float a, float b) {
    __half2 h = __floats2half2_rn(a, b);
    return *(unsigned*)&h;
}
__device__ __forceinline__ void mma_f16(float* c, unsigned a0, unsigned a1, unsigned a2, unsigned a3,
                                        unsigned b0, unsigned b1) {
    asm volatile(
        "mma.sync.aligned.m16n8k16.row.col.f32.f16.f16.f32 "
        "{%0,%1,%2,%3},{%4,%5,%6,%7},{%8,%9},{%0,%1,%2,%3};"
        : "+f"(c[0]), "+f"(c[1]), "+f"(c[2]), "+f"(c[3])
        : "r"(a0), "r"(a1), "r"(a2), "r"(a3), "r"(b0), "r"(b1));
}
__device__ __forceinline__ unsigned smem_u32(const void* p) {
    unsigned a;
    asm("{ .reg .u64 t; cvta.to.shared.u64 t, %1; cvt.u32.u64 %0, t; }" : "=r"(a) : "l"(p));
    return a;
}
// 16-byte async copy with zero-fill when !pred (src must still be a valid pointer)
__device__ __forceinline__ void cp16(unsigned dst_smem, const void* src, bool pred) {
    int sz = pred ? 16 : 0;
    asm volatile("cp.async.cg.shared.global [%0], [%1], 16, %2;"
                 :: "r"(dst_smem), "l"(src), "r"(sz));
}
__device__ __forceinline__ void cp_commit() { asm volatile("cp.async.commit_group;"); }
template <int N>
__device__ __forceinline__ void cp_wait() { asm volatile("cp.async.wait_group %0;" :: "n"(N)); }

// ---------------- small kernels ----------------
__global__ void zero_stats_kernel(double* s, double* q) {
    int i = threadIdx.x;
    if (i < 96) { s[i] = 0.0; q[i] = 0.0; }
}

__global__ void wext_kernel(const float* __restrict__ W, unsigned* __restrict__ dst,
                            int COUT, int CINF, int n) {
    int i = blockIdx.x * blockDim.x + threadIdx.x;
    if (i >= n) return;
    int j  = i % 44;
    int co = (i / 44) % COUT;
    int dy = (i / (44 * COUT)) % 5;
    int s  = i / (220 * COUT);
    int g = s / 25, tap = s % 25, dt = tap / 5, dz = tap % 5;
    unsigned val = 0;
    if (j < 40) {
        int dx = j / 8, ci = 2 * (j % 8);
        long base = dt * 125 + dz * 25 + dy * 5 + dx;
        float w0 = W[((long)co * CINF + g * 16 + ci) * 625 + base];
        float w1 = W[((long)co * CINF + g * 16 + ci + 1) * 625 + base];
        val = packh2(w0, w1);
    }
    dst[i] = val;
}

__global__ void embed_kernel(const float* __restrict__ x, const float* __restrict__ we,
                             const float* __restrict__ be, unsigned* __restrict__ act) {
    __shared__ float sw[F * H];
    __shared__ float sb[H];
    if (threadIdx.x < F * H) sw[threadIdx.x] = we[threadIdx.x];
    if (threadIdx.x < H) sb[threadIdx.x] = be[threadIdx.x];
    __syncthreads();
    int v = blockIdx.x * blockDim.x + threadIdx.x;
    if (v >= NV) return;
    const float4* xp = (const float4*)(x + v * F);
    float4 x0 = xp[0], x1 = xp[1];
    float xf[F] = {x0.x, x0.y, x0.z, x0.w, x1.x, x1.y, x1.z, x1.w};
    float o[H];
#pragma unroll
    for (int h = 0; h < H; h++) {
        float a = sb[h];
#pragma unroll
        for (int f = 0; f < F; f++) a += xf[f] * sw[f * H + h];
        o[h] = a;
    }
    unsigned p[8];
#pragma unroll
    for (int q = 0; q < 8; q++) p[q] = packh2(o[2*q], o[2*q+1]);
    uint4* dst = (uint4*)(act + (long)v * 8);
    dst[0] = make_uint4(p[0], p[1], p[2], p[3]);
    dst[1] = make_uint4(p[4], p[5], p[6], p[7]);
}

// ---------------- tensor-core 4D conv (fp16 k16) + cp.async double buffer + fused BN stats ----
// CTA = (b,d1,d2) x 8 d3-rows, M=256 voxels. 8 warps x 2 m16-tiles.
// A smem: [srow12][d4p36] cell = 12 u32 (16 fp16 + pad) -> conflict-free scalar LDS.
template <int COUT, int SLABS>
__global__ void __launch_bounds__(256)
conv_mma_kernel(const unsigned* __restrict__ act, const unsigned* __restrict__ wext,
                const float* __restrict__ bias, float* __restrict__ fout,
                double* __restrict__ gsum, double* __restrict__ gssq) {
    constexpr int NT = COUT / 8;
    constexpr int SA_U32 = 12 * 36 * 12;          // 5184 per buffer
    constexpr int SW_U32 = 5 * COUT * 44;         // per buffer
    extern __shared__ unsigned smem_u[];
    unsigned* sAbuf[2] = {smem_u, smem_u + SA_U32};
    unsigned* sWbuf[2] = {smem_u + 2 * SA_U32, smem_u + 2 * SA_U32 + SW_U32};
    float* s_st = (float*)(smem_u + 2 * SA_U32 + 2 * SW_U32);   // [2*COUT]

    int bi = blockIdx.x;
    int d3b = (bi & 3) * 8;
    int rest = bi >> 2;
    int d2 = rest & 15, d1 = (rest >> 4) & 7, b = rest >> 7;

    int tid = threadIdx.x, lane = tid & 31, wid = tid >> 5;
    int d3r0 = wid >> 1, h = wid & 1;
    int lq = lane >> 2, lr = lane & 3;

    for (int i = tid; i < 2 * COUT; i += 256) s_st[i] = 0.f;

    float acc[2][NT][4];
#pragma unroll
    for (int t = 0; t < 2; t++)
#pragma unroll
        for (int n = 0; n < NT; n++) {
            float b0 = bias[n * 8 + 2 * lr], b1v = bias[n * 8 + 2 * lr + 1];
            acc[t][n][0] = b0; acc[t][n][1] = b1v; acc[t][n][2] = b0; acc[t][n][3] = b1v;
        }

    const uint4* actu4 = (const uint4*)act;
    const uint4* wxu4  = (const uint4*)wext;

    // async stage of slab s into buffer bufi
    auto stage = [&](int s, int bufi) {
        int g = s / 25, tap = s % 25;
        int dt = tap / 5, dz = tap % 5;
        int d1s = d1 + dt - 2, d2s = d2 + dz - 2;
        bool v12 = ((unsigned)d1s < 8u) && ((unsigned)d2s < 16u);
        int pbase = g * NV;
        int vb = ((b * 8 + d1s) * 16 + d2s) * 1024;
        unsigned* dA = sAbuf[bufi];
        unsigned* dW = sWbuf[bufi];
        for (int i = tid; i < 864; i += 256) {
            int q = i & 1, cell = i >> 1;
            int d4p = cell % 36, srow = cell / 36;
            int d3s = d3b + srow - 2;
            bool ok = v12 && (unsigned)d3s < 32u && d4p >= 2 && d4p < 34;
            const uint4* src = ok ? &actu4[((long)(pbase + vb + d3s * 32 + d4p - 2) << 1) + q]
                                  : actu4;
            cp16(smem_u32(dA + cell * 12 + q * 4), src, ok);
        }
        const uint4* wsrc = wxu4 + (long)s * (SW_U32 / 4);
        for (int i = tid; i < SW_U32 / 4; i += 256)
            cp16(smem_u32(dW + i * 4), wsrc + i, true);
        cp_commit();
    };

    stage(0, 0);

    for (int s = 0; s < SLABS; s++) {
        int bufi = s & 1;
        if (s + 1 < SLABS) {
            stage(s + 1, bufi ^ 1);
            cp_wait<1>();
        } else {
            cp_wait<0>();
        }
        __syncthreads();

        const unsigned* sA = sAbuf[bufi];
        const unsigned* sW = sWbuf[bufi];

#pragma unroll 1
        for (int dy = 0; dy < 5; dy++) {
            int ar0 = ((d3r0 + dy) * 36 + h * 16 + lq) * 12 + lr;   // m-tile0, row lq
            int ar1 = ar0 + 96;                                      // row lq+8
            int br0 = ar0 + 1728;                                    // m-tile1 (+4 d3rows)
            int br1 = br0 + 96;
            int wb = (dy * COUT + lq) * 44 + lr;
#pragma unroll
            for (int kc = 0; kc < 5; kc++) {
                int ko = kc * 12;
                unsigned a00 = sA[ar0 + ko], a01 = sA[ar1 + ko];
                unsigned a02 = sA[ar0 + ko + 4], a03 = sA[ar1 + ko + 4];
                unsigned a10 = sA[br0 + ko], a11 = sA[br1 + ko];
                unsigned a12 = sA[br0 + ko + 4], a13 = sA[br1 + ko + 4];
#pragma unroll
                for (int n = 0; n < NT; n++) {
                    unsigned b0 = sW[wb + n * 352 + kc * 8];
                    unsigned b1 = sW[wb + n * 352 + kc * 8 + 4];
                    mma_f16(acc[0][n], a00, a01, a02, a03, b0, b1);
                    mma_f16(acc[1][n], a10, a11, a12, a13, b0, b1);
                }
            }
        }
        __syncthreads();   // protect buffer bufi before it is re-staged at s+2
    }

    // epilogue: store fp32 + fused BN stats
    int vox0 = ((b * 8 + d1) * 16 + d2) * 1024 + d3b * 32;
#pragma unroll
    for (int t = 0; t < 2; t++) {
        int d3r = d3r0 + 4 * t;
        long base = (long)(vox0 + d3r * 32 + h * 16 + lq) * COUT + 2 * lr;
#pragma unroll
        for (int n = 0; n < NT; n++) {
            *(float2*)&fout[base + n * 8]            = make_float2(acc[t][n][0], acc[t][n][1]);
            *(float2*)&fout[base + 8 * COUT + n * 8] = make_float2(acc[t][n][2], acc[t][n][3]);
        }
    }
#pragma unroll
    for (int n = 0; n < NT; n++) {
        float s0 = 0.f, s1 = 0.f, q0 = 0.f, q1 = 0.f;
#pragma unroll
        for (int t = 0; t < 2; t++) {
            s0 += acc[t][n][0] + acc[t][n][2];
            s1 += acc[t][n][1] + acc[t][n][3];
            q0 += acc[t][n][0] * acc[t][n][0] + acc[t][n][2] * acc[t][n][2];
            q1 += acc[t][n][1] * acc[t][n][1] + acc[t][n][3] * acc[t][n][3];
        }
#pragma unroll
        for (int off = 16; off >= 4; off >>= 1) {
            s0 += __shfl_down_sync(0xffffffffu, s0, off);
            s1 += __shfl_down_sync(0xffffffffu, s1, off);
            q0 += __shfl_down_sync(0xffffffffu, q0, off);
            q1 += __shfl_down_sync(0xffffffffu, q1, off);
        }
        if (lq == 0) {
            int ch = n * 8 + 2 * lr;
            atomicAdd(&s_st[ch], s0);
            atomicAdd(&s_st[ch + 1], s1);
            atomicAdd(&s_st[COUT + ch], q0);
            atomicAdd(&s_st[COUT + ch + 1], q1);
        }
    }
    __syncthreads();
    if (tid < COUT)          atomicAdd(&gsum[tid], (double)s_st[tid]);
    else if (tid < 2 * COUT) atomicAdd(&gssq[tid - COUT], (double)s_st[tid]);
}

// ---------------- bn apply (+ leaky relu) -> fp16 planes ----------------
template <int C>
__global__ void bn_apply_kernel(const float* __restrict__ fout, const double* __restrict__ sum,
                                const double* __restrict__ ssq, const float* __restrict__ gamma,
                                const float* __restrict__ beta, unsigned* __restrict__ act) {
    constexpr int NPL = C / 16;
    __shared__ float sc[C], sh[C];
    int tid = threadIdx.x;
    if (tid < C) {
        double m   = sum[tid] / (double)NV;
        double var = ssq[tid] / (double)NV - m * m;
        double inv = 1.0 / sqrt(var + 1e-5);
        float s = gamma[tid] * (float)inv;
        sc[tid] = s;
        sh[tid] = beta[tid] - (float)m * s;
    }
    __syncthreads();
    long total  = (long)NV * NPL;
    long stride = (long)gridDim.x * blockDim.x;
    for (long id = blockIdx.x * (long)blockDim.x + tid; id < total; id += stride) {
        int vox = (int)(id % NV);
        int pl  = (int)(id / NV);
        const float4* src = (const float4*)&fout[(long)vox * C + pl * 16];
        float4 v0 = src[0], v1 = src[1], v2 = src[2], v3 = src[3];
        float vv[16] = {v0.x, v0.y, v0.z, v0.w, v1.x, v1.y, v1.z, v1.w,
                        v2.x, v2.y, v2.z, v2.w, v3.x, v3.y, v3.z, v3.w};
        unsigned p[8];
#pragma unroll
        for (int q = 0; q < 8; q++) {
            float r0 = vv[2*q]   * sc[pl*16 + 2*q]   + sh[pl*16 + 2*q];
            float r1 = vv[2*q+1] * sc[pl*16 + 2*q+1] + sh[pl*16 + 2*q+1];
            r0 = fmaxf(r0, LRELU * r0);
            r1 = fmaxf(r1, LRELU * r1);
            p[q] = packh2(r0, r1);
        }
        uint4* dst = (uint4*)&act[((long)pl * NV + vox) * 8];
        dst[0] = make_uint4(p[0], p[1], p[2], p[3]);
        dst[1] = make_uint4(p[4], p[5], p[6], p[7]);
    }
}

// ---------------- fused BN + leaky relu + projection (layer 3) ----------------
__global__ void bnproj_kernel(const float* __restrict__ fout, const double* __restrict__ sum,
                              const double* __restrict__ ssq, const float* __restrict__ gamma,
                              const float* __restrict__ beta, const float* __restrict__ wp,
                              const float* __restrict__ bp, float* __restrict__ out) {
    __shared__ float sc[H], sh[H], sw[H];
    __shared__ float sb;
    int tid = threadIdx.x;
    if (tid < H) {
        double m   = sum[tid] / (double)NV;
        double var = ssq[tid] / (double)NV - m * m;
        double inv = 1.0 / sqrt(var + 1e-5);
        float s = gamma[tid] * (float)inv;
        sc[tid] = s;
        sh[tid] = beta[tid] - (float)m * s;
        sw[tid] = wp[tid];
    }
    if (tid == 0) sb = bp[0];
    __syncthreads();
    int v = blockIdx.x * blockDim.x + tid;
    if (v >= NV) return;
    const float4* src = (const float4*)&fout[(long)v * H];
    float4 v0 = src[0], v1 = src[1], v2 = src[2], v3 = src[3];
    float vv[16] = {v0.x, v0.y, v0.z, v0.w, v1.x, v1.y, v1.z, v1.w,
                    v2.x, v2.y, v2.z, v2.w, v3.x, v3.y, v3.z, v3.w};
    float a = sb;
#pragma unroll
    for (int c = 0; c < H; c++) {
        float r = vv[c] * sc[c] + sh[c];
        r = fmaxf(r, LRELU * r);
        a += r * sw[c];
    }
    out[v] = a;
}

// ---------------- launch ----------------
extern "C" void kernel_launch(void* const* d_in, const int* in_sizes, int n_in,
                              void* d_out, int out_size) {
    const float* x      = (const float*)d_in[0];
    const float* w_emb  = (const float*)d_in[1];
    const float* b_emb  = (const float*)d_in[2];
    const float* W1     = (const float*)d_in[3];
    const float* b1     = (const float*)d_in[4];
    const float* g1     = (const float*)d_in[5];
    const float* be1    = (const float*)d_in[6];
    const float* W2     = (const float*)d_in[7];
    const float* b2     = (const float*)d_in[8];
    const float* g2     = (const float*)d_in[9];
    const float* be2    = (const float*)d_in[10];
    const float* W3     = (const float*)d_in[11];
    const float* b3     = (const float*)d_in[12];
    const float* g3     = (const float*)d_in[13];
    const float* be3    = (const float*)d_in[14];
    const float* w_proj = (const float*)d_in[15];
    const float* b_proj = (const float*)d_in[16];

    unsigned *actA, *actB, *actC, *wx1, *wx2, *wx3;
    float* fout;
    double *sums, *ssqs;
    cudaGetSymbolAddress((void**)&actA, g_actA);
    cudaGetSymbolAddress((void**)&actB, g_actB);
    cudaGetSymbolAddress((void**)&actC, g_actC);
    cudaGetSymbolAddress((void**)&fout, g_fout);
    cudaGetSymbolAddress((void**)&wx1, g_wx1);
    cudaGetSymbolAddress((void**)&wx2, g_wx2);
    cudaGetSymbolAddress((void**)&wx3, g_wx3);
    cudaGetSymbolAddress((void**)&sums, g_sum);
    cudaGetSymbolAddress((void**)&ssqs, g_ssq);

    // smem: 2*A(20736) + 2*W(5*COUT*44*4) + stats
    // conv1/3: 41472 + 28160 + 128 = 69760 ; conv2: 41472 + 56320 + 256 = 98048
    cudaFuncSetAttribute(conv_mma_kernel<16, 25>, cudaFuncAttributeMaxDynamicSharedMemorySize, 69760);
    cudaFuncSetAttribute(conv_mma_kernel<32, 25>, cudaFuncAttributeMaxDynamicSharedMemorySize, 98048);
    cudaFuncSetAttribute(conv_mma_kernel<16, 50>, cudaFuncAttributeMaxDynamicSharedMemorySize, 69760);

    zero_stats_kernel<<<1, 128>>>(sums, ssqs);
    wext_kernel<<<(88000 + 255) / 256, 256>>>(W1, wx1, 16, 16, 88000);
    wext_kernel<<<(176000 + 255) / 256, 256>>>(W2, wx2, 32, 16, 176000);
    wext_kernel<<<(176000 + 255) / 256, 256>>>(W3, wx3, 16, 32, 176000);

    embed_kernel<<<NV / 256, 256>>>(x, w_emb, b_emb, actA);

    conv_mma_kernel<16, 25><<<1024, 256, 69760>>>(actA, wx1, b1, fout, sums + 0, ssqs + 0);
    bn_apply_kernel<16><<<1024, 256>>>(fout, sums + 0, ssqs + 0, g1, be1, actB);

    conv_mma_kernel<32, 25><<<1024, 256, 98048>>>(actB, wx2, b2, fout, sums + 32, ssqs + 32);
    bn_apply_kernel<32><<<2048, 256>>>(fout, sums + 32, ssqs + 32, g2, be2, actC);

    conv_mma_kernel<16, 50><<<1024, 256, 69760>>>(actC, wx3, b3, fout, sums + 64, ssqs + 64);
    bnproj_kernel<<<NV / 256, 256>>>(fout, sums + 64, ssqs + 64, g3, be3, w_proj, b_proj, (float*)d_out);
}

// round 11
// speedup vs baseline: 1.7245x; 1.2587x over previous
#include <cuda_runtime.h>
#include <cuda_fp16.h>

// ---------------- problem dims ----------------
constexpr int B = 2, D1 = 8, D2 = 16, D3 = 32, D4 = 32, F = 8, H = 16, H2 = 32;
constexpr int NV = B * D1 * D2 * D3 * D4;  // 262144 voxels
constexpr float LRELU = 0.01f;

// ---------------- static scratch ----------------
__device__ unsigned g_actA[(long)NV * 8];         // conv1 input
__device__ unsigned g_actB[(long)NV * 8];         // conv2 input
__device__ unsigned g_actC[(long)NV * 16];        // conv3 input (2 planes)
__device__ float    g_fout[(long)NV * 32];        // conv fp32 output (reused)
// expanded fp16 weights: [slab][dy][cout][44 u32]
__device__ unsigned g_wx1[25 * 5 * 16 * 44];
__device__ unsigned g_wx2[25 * 5 * 32 * 44];
__device__ unsigned g_wx3[50 * 5 * 16 * 44];
__device__ double g_sum[3 * 32];
__device__ double g_ssq[3 * 32];

// ---------------- helpers ----------------
__device__ __forceinline__ unsigned packh2(float a, float b) {
    __half2 h = __floats2half2_rn(a, b);
    return *(unsigned*)&h;
}
__device__ __forceinline__ void mma_f16(float* c, unsigned a0, unsigned a1, unsigned a2, unsigned a3,
                                        unsigned b0, unsigned b1) {
    asm volatile(
        "mma.sync.aligned.m16n8k16.row.col.f32.f16.f16.f32 "
        "{%0,%1,%2,%3},{%4,%5,%6,%7},{%8,%9},{%0,%1,%2,%3};"
        : "+f"(c[0]), "+f"(c[1]), "+f"(c[2]), "+f"(c[3])
        : "r"(a0), "r"(a1), "r"(a2), "r"(a3), "r"(b0), "r"(b1));
}

// ---------------- small kernels ----------------
__global__ void zero_stats_kernel(double* s, double* q) {
    int i = threadIdx.x;
    if (i < 96) { s[i] = 0.0; q[i] = 0.0; }
}

__global__ void wext_kernel(const float* __restrict__ W, unsigned* __restrict__ dst,
                            int COUT, int CINF, int n) {
    int i = blockIdx.x * blockDim.x + threadIdx.x;
    if (i >= n) return;
    int j  = i % 44;
    int co = (i / 44) % COUT;
    int dy = (i / (44 * COUT)) % 5;
    int s  = i / (220 * COUT);
    int g = s / 25, tap = s % 25, dt = tap / 5, dz = tap % 5;
    unsigned val = 0;
    if (j < 40) {
        int dx = j / 8, ci = 2 * (j % 8);
        long base = dt * 125 + dz * 25 + dy * 5 + dx;
        float w0 = W[((long)co * CINF + g * 16 + ci) * 625 + base];
        float w1 = W[((long)co * CINF + g * 16 + ci + 1) * 625 + base];
        val = packh2(w0, w1);
    }
    dst[i] = val;
}

__global__ void embed_kernel(const float* __restrict__ x, const float* __restrict__ we,
                             const float* __restrict__ be, unsigned* __restrict__ act) {
    __shared__ float sw[F * H];
    __shared__ float sb[H];
    if (threadIdx.x < F * H) sw[threadIdx.x] = we[threadIdx.x];
    if (threadIdx.x < H) sb[threadIdx.x] = be[threadIdx.x];
    __syncthreads();
    int v = blockIdx.x * blockDim.x + threadIdx.x;
    if (v >= NV) return;
    const float4* xp = (const float4*)(x + v * F);
    float4 x0 = xp[0], x1 = xp[1];
    float xf[F] = {x0.x, x0.y, x0.z, x0.w, x1.x, x1.y, x1.z, x1.w};
    float o[H];
#pragma unroll
    for (int h = 0; h < H; h++) {
        float a = sb[h];
#pragma unroll
        for (int f = 0; f < F; f++) a += xf[f] * sw[f * H + h];
        o[h] = a;
    }
    unsigned p[8];
#pragma unroll
    for (int q = 0; q < 8; q++) p[q] = packh2(o[2*q], o[2*q+1]);
    uint4* dst = (uint4*)(act + (long)v * 8);
    dst[0] = make_uint4(p[0], p[1], p[2], p[3]);
    dst[1] = make_uint4(p[4], p[5], p[6], p[7]);
}

// ---------------- tensor-core 4D conv (fp16 k16) + register-pipelined staging + fused BN stats ----
// CTA = (b,d1,d2) x 8 d3-rows, M=256 voxels. 8 warps x 2 m16-tiles.
// A smem: [srow12][d4p36] cell = 12 u32 (16 fp16 + pad) -> conflict-free scalar LDS.
// Staging pipeline: regs hold slab s while LDGs for s+1 fly during compute(s).
template <int COUT, int SLABS>
__global__ void __launch_bounds__(256)
conv_mma_kernel(const unsigned* __restrict__ act, const unsigned* __restrict__ wext,
                const float* __restrict__ bias, float* __restrict__ fout,
                double* __restrict__ gsum, double* __restrict__ gssq) {
    constexpr int NT = COUT / 8;
    constexpr int SA_U32 = 12 * 36 * 12;          // 5184
    constexpr int SW_U32 = 5 * COUT * 44;
    constexpr int NW4 = SW_U32 / 4;               // uint4 count of W slab
    constexpr int NWIT = (NW4 + 255) / 256;       // 1 (COUT=16) or 2 (COUT=32)
    extern __shared__ unsigned smem_u[];
    unsigned* sA = smem_u;
    unsigned* sW = smem_u + SA_U32;
    float* s_st  = (float*)(smem_u + SA_U32 + SW_U32);   // [2*COUT]

    int bi = blockIdx.x;
    int d3b = (bi & 3) * 8;
    int rest = bi >> 2;
    int d2 = rest & 15, d1 = (rest >> 4) & 7, b = rest >> 7;

    int tid = threadIdx.x, lane = tid & 31, wid = tid >> 5;
    int d3r0 = wid >> 1, h = wid & 1;
    int lq = lane >> 2, lr = lane & 3;

    for (int i = tid; i < 2 * COUT; i += 256) s_st[i] = 0.f;

    float acc[2][NT][4];
#pragma unroll
    for (int t = 0; t < 2; t++)
#pragma unroll
        for (int n = 0; n < NT; n++) {
            float b0 = bias[n * 8 + 2 * lr], b1v = bias[n * 8 + 2 * lr + 1];
            acc[t][n][0] = b0; acc[t][n][1] = b1v; acc[t][n][2] = b0; acc[t][n][3] = b1v;
        }

    const uint4* actu4 = (const uint4*)act;
    const uint4* wxu4  = (const uint4*)wext;

    uint4 ra[4];
    uint4 rw[NWIT];

    // issue LDGs for slab s into registers
    auto ldg_slab = [&](int s) {
        int g = s / 25, tap = s % 25;
        int dt = tap / 5, dz = tap % 5;
        int d1s = d1 + dt - 2, d2s = d2 + dz - 2;
        bool v12 = ((unsigned)d1s < 8u) && ((unsigned)d2s < 16u);
        int pbase = g * NV;
        int vb = ((b * 8 + d1s) * 16 + d2s) * 1024;
#pragma unroll
        for (int it = 0; it < 4; it++) {
            int i = tid + it * 256;
            ra[it] = make_uint4(0, 0, 0, 0);
            if (i < 864) {
                int q = i & 1, cell = i >> 1;
                int d4p = cell % 36, srow = cell / 36;
                int d3s = d3b + srow - 2;
                if (v12 && (unsigned)d3s < 32u && d4p >= 2 && d4p < 34)
                    ra[it] = actu4[((long)(pbase + vb + d3s * 32 + d4p - 2) << 1) + q];
            }
        }
        const uint4* wsrc = wxu4 + (long)s * NW4;
#pragma unroll
        for (int jt = 0; jt < NWIT; jt++) {
            int j = tid + jt * 256;
            if (j < NW4) rw[jt] = wsrc[j];
        }
    };

    ldg_slab(0);

    for (int s = 0; s < SLABS; s++) {
        __syncthreads();   // previous compute done reading smem
        // STS: registers (slab s) -> smem
#pragma unroll
        for (int it = 0; it < 4; it++) {
            int i = tid + it * 256;
            if (i < 864) {
                int q = i & 1, cell = i >> 1;
                *(uint4*)(sA + cell * 12 + q * 4) = ra[it];
            }
        }
#pragma unroll
        for (int jt = 0; jt < NWIT; jt++) {
            int j = tid + jt * 256;
            if (j < NW4) ((uint4*)sW)[j] = rw[jt];
        }
        // prefetch slab s+1 (lands during compute below)
        if (s + 1 < SLABS) ldg_slab(s + 1);
        __syncthreads();

#pragma unroll 1
        for (int dy = 0; dy < 5; dy++) {
            int ar0 = ((d3r0 + dy) * 36 + h * 16 + lq) * 12 + lr;   // m-tile0, row lq
            int ar1 = ar0 + 96;                                      // row lq+8
            int br0 = ar0 + 1728;                                    // m-tile1 (+4 d3rows)
            int br1 = br0 + 96;
            int wb = (dy * COUT + lq) * 44 + lr;
#pragma unroll
            for (int kc = 0; kc < 5; kc++) {
                int ko = kc * 12;
                unsigned a00 = sA[ar0 + ko], a01 = sA[ar1 + ko];
                unsigned a02 = sA[ar0 + ko + 4], a03 = sA[ar1 + ko + 4];
                unsigned a10 = sA[br0 + ko], a11 = sA[br1 + ko];
                unsigned a12 = sA[br0 + ko + 4], a13 = sA[br1 + ko + 4];
#pragma unroll
                for (int n = 0; n < NT; n++) {
                    unsigned b0 = sW[wb + n * 352 + kc * 8];
                    unsigned b1 = sW[wb + n * 352 + kc * 8 + 4];
                    mma_f16(acc[0][n], a00, a01, a02, a03, b0, b1);
                    mma_f16(acc[1][n], a10, a11, a12, a13, b0, b1);
                }
            }
        }
    }

    // epilogue: store fp32 + fused BN stats
    int vox0 = ((b * 8 + d1) * 16 + d2) * 1024 + d3b * 32;
#pragma unroll
    for (int t = 0; t < 2; t++) {
        int d3r = d3r0 + 4 * t;
        long base = (long)(vox0 + d3r * 32 + h * 16 + lq) * COUT + 2 * lr;
#pragma unroll
        for (int n = 0; n < NT; n++) {
            *(float2*)&fout[base + n * 8]            = make_float2(acc[t][n][0], acc[t][n][1]);
            *(float2*)&fout[base + 8 * COUT + n * 8] = make_float2(acc[t][n][2], acc[t][n][3]);
        }
    }
#pragma unroll
    for (int n = 0; n < NT; n++) {
        float s0 = 0.f, s1 = 0.f, q0 = 0.f, q1 = 0.f;
#pragma unroll
        for (int t = 0; t < 2; t++) {
            s0 += acc[t][n][0] + acc[t][n][2];
            s1 += acc[t][n][1] + acc[t][n][3];
            q0 += acc[t][n][0] * acc[t][n][0] + acc[t][n][2] * acc[t][n][2];
            q1 += acc[t][n][1] * acc[t][n][1] + acc[t][n][3] * acc[t][n][3];
        }
#pragma unroll
        for (int off = 16; off >= 4; off >>= 1) {
            s0 += __shfl_down_sync(0xffffffffu, s0, off);
            s1 += __shfl_down_sync(0xffffffffu, s1, off);
            q0 += __shfl_down_sync(0xffffffffu, q0, off);
            q1 += __shfl_down_sync(0xffffffffu, q1, off);
        }
        if (lq == 0) {
            int ch = n * 8 + 2 * lr;
            atomicAdd(&s_st[ch], s0);
            atomicAdd(&s_st[ch + 1], s1);
            atomicAdd(&s_st[COUT + ch], q0);
            atomicAdd(&s_st[COUT + ch + 1], q1);
        }
    }
    __syncthreads();
    if (tid < COUT)          atomicAdd(&gsum[tid], (double)s_st[tid]);
    else if (tid < 2 * COUT) atomicAdd(&gssq[tid - COUT], (double)s_st[tid]);
}

// ---------------- bn apply (+ leaky relu) -> fp16 planes ----------------
template <int C>
__global__ void bn_apply_kernel(const float* __restrict__ fout, const double* __restrict__ sum,
                                const double* __restrict__ ssq, const float* __restrict__ gamma,
                                const float* __restrict__ beta, unsigned* __restrict__ act) {
    constexpr int NPL = C / 16;
    __shared__ float sc[C], sh[C];
    int tid = threadIdx.x;
    if (tid < C) {
        double m   = sum[tid] / (double)NV;
        double var = ssq[tid] / (double)NV - m * m;
        double inv = 1.0 / sqrt(var + 1e-5);
        float s = gamma[tid] * (float)inv;
        sc[tid] = s;
        sh[tid] = beta[tid] - (float)m * s;
    }
    __syncthreads();
    long total  = (long)NV * NPL;
    long stride = (long)gridDim.x * blockDim.x;
    for (long id = blockIdx.x * (long)blockDim.x + tid; id < total; id += stride) {
        int vox = (int)(id % NV);
        int pl  = (int)(id / NV);
        const float4* src = (const float4*)&fout[(long)vox * C + pl * 16];
        float4 v0 = src[0], v1 = src[1], v2 = src[2], v3 = src[3];
        float vv[16] = {v0.x, v0.y, v0.z, v0.w, v1.x, v1.y, v1.z, v1.w,
                        v2.x, v2.y, v2.z, v2.w, v3.x, v3.y, v3.z, v3.w};
        unsigned p[8];
#pragma unroll
        for (int q = 0; q < 8; q++) {
            float r0 = vv[2*q]   * sc[pl*16 + 2*q]   + sh[pl*16 + 2*q];
            float r1 = vv[2*q+1] * sc[pl*16 + 2*q+1] + sh[pl*16 + 2*q+1];
            r0 = fmaxf(r0, LRELU * r0);
            r1 = fmaxf(r1, LRELU * r1);
            p[q] = packh2(r0, r1);
        }
        uint4* dst = (uint4*)&act[((long)pl * NV + vox) * 8];
        dst[0] = make_uint4(p[0], p[1], p[2], p[3]);
        dst[1] = make_uint4(p[4], p[5], p[6], p[7]);
    }
}

// ---------------- fused BN + leaky relu + projection (layer 3) ----------------
__global__ void bnproj_kernel(const float* __restrict__ fout, const double* __restrict__ sum,
                              const double* __restrict__ ssq, const float* __restrict__ gamma,
                              const float* __restrict__ beta, const float* __restrict__ wp,
                              const float* __restrict__ bp, float* __restrict__ out) {
    __shared__ float sc[H], sh[H], sw[H];
    __shared__ float sb;
    int tid = threadIdx.x;
    if (tid < H) {
        double m   = sum[tid] / (double)NV;
        double var = ssq[tid] / (double)NV - m * m;
        double inv = 1.0 / sqrt(var + 1e-5);
        float s = gamma[tid] * (float)inv;
        sc[tid] = s;
        sh[tid] = beta[tid] - (float)m * s;
        sw[tid] = wp[tid];
    }
    if (tid == 0) sb = bp[0];
    __syncthreads();
    int v = blockIdx.x * blockDim.x + tid;
    if (v >= NV) return;
    const float4* src = (const float4*)&fout[(long)v * H];
    float4 v0 = src[0], v1 = src[1], v2 = src[2], v3 = src[3];
    float vv[16] = {v0.x, v0.y, v0.z, v0.w, v1.x, v1.y, v1.z, v1.w,
                    v2.x, v2.y, v2.z, v2.w, v3.x, v3.y, v3.z, v3.w};
    float a = sb;
#pragma unroll
    for (int c = 0; c < H; c++) {
        float r = vv[c] * sc[c] + sh[c];
        r = fmaxf(r, LRELU * r);
        a += r * sw[c];
    }
    out[v] = a;
}

// ---------------- launch ----------------
extern "C" void kernel_launch(void* const* d_in, const int* in_sizes, int n_in,
                              void* d_out, int out_size) {
    const float* x      = (const float*)d_in[0];
    const float* w_emb  = (const float*)d_in[1];
    const float* b_emb  = (const float*)d_in[2];
    const float* W1     = (const float*)d_in[3];
    const float* b1     = (const float*)d_in[4];
    const float* g1     = (const float*)d_in[5];
    const float* be1    = (const float*)d_in[6];
    const float* W2     = (const float*)d_in[7];
    const float* b2     = (const float*)d_in[8];
    const float* g2     = (const float*)d_in[9];
    const float* be2    = (const float*)d_in[10];
    const float* W3     = (const float*)d_in[11];
    const float* b3     = (const float*)d_in[12];
    const float* g3     = (const float*)d_in[13];
    const float* be3    = (const float*)d_in[14];
    const float* w_proj = (const float*)d_in[15];
    const float* b_proj = (const float*)d_in[16];

    unsigned *actA, *actB, *actC, *wx1, *wx2, *wx3;
    float* fout;
    double *sums, *ssqs;
    cudaGetSymbolAddress((void**)&actA, g_actA);
    cudaGetSymbolAddress((void**)&actB, g_actB);
    cudaGetSymbolAddress((void**)&actC, g_actC);
    cudaGetSymbolAddress((void**)&fout, g_fout);
    cudaGetSymbolAddress((void**)&wx1, g_wx1);
    cudaGetSymbolAddress((void**)&wx2, g_wx2);
    cudaGetSymbolAddress((void**)&wx3, g_wx3);
    cudaGetSymbolAddress((void**)&sums, g_sum);
    cudaGetSymbolAddress((void**)&ssqs, g_ssq);

    // smem: A 20736 + W (5*COUT*44*4) + stats
    cudaFuncSetAttribute(conv_mma_kernel<16, 25>, cudaFuncAttributeMaxDynamicSharedMemorySize, 34944);
    cudaFuncSetAttribute(conv_mma_kernel<32, 25>, cudaFuncAttributeMaxDynamicSharedMemorySize, 49152);
    cudaFuncSetAttribute(conv_mma_kernel<16, 50>, cudaFuncAttributeMaxDynamicSharedMemorySize, 34944);

    zero_stats_kernel<<<1, 128>>>(sums, ssqs);
    wext_kernel<<<(88000 + 255) / 256, 256>>>(W1, wx1, 16, 16, 88000);
    wext_kernel<<<(176000 + 255) / 256, 256>>>(W2, wx2, 32, 16, 176000);
    wext_kernel<<<(176000 + 255) / 256, 256>>>(W3, wx3, 16, 32, 176000);

    embed_kernel<<<NV / 256, 256>>>(x, w_emb, b_emb, actA);

    conv_mma_kernel<16, 25><<<1024, 256, 34944>>>(actA, wx1, b1, fout, sums + 0, ssqs + 0);
    bn_apply_kernel<16><<<1024, 256>>>(fout, sums + 0, ssqs + 0, g1, be1, actB);

    conv_mma_kernel<32, 25><<<1024, 256, 49152>>>(actB, wx2, b2, fout, sums + 32, ssqs + 32);
    bn_apply_kernel<32><<<2048, 256>>>(fout, sums + 32, ssqs + 32, g2, be2, actC);

    conv_mma_kernel<16, 50><<<1024, 256, 34944>>>(actC, wx3, b3, fout, sums + 64, ssqs + 64);
    bnproj_kernel<<<NV / 256, 256>>>(fout, sums + 64, ssqs + 64, g3, be3, w_proj, b_proj, (float*)d_out);
}